// round 13
// baseline (speedup 1.0000x reference)
#include <cuda_runtime.h>
#include <cuda_fp16.h>

// Geometry: (N=2, C=1, D=160, H=192, W=224), win=9, pad=4, zero-padded box sums.
#define NB   2
#define DD   160
#define HH   192
#define WW   224
#define HW   (HH * WW)            // 43008
#define DHW  (DD * HW)            // 6881280
#define VOLI (NB * DHW)           // 13762560
#define PAD  4
#define EPSV 1e-5f
#define SZ   ((size_t)VOLI)

#define CH     64                 // h-chunk per block in kA
#define NSTEPS (CH + 2 * PAD)     // 72
#define ROWL   (WW + 2 * PAD)     // 232

#define CHD  80                   // d-chunk per thread in k3
#define NCD  2
#define W2   (WW / 2)             // 112 voxel-pairs per row
#define T3B  (NB * NCD * HH * W2) // 86016 threads (2 voxels each)
#define K3_BLOCKS (T3B / 256)     // 336

// Scratch: W+H box-summed fields in FP16 (values <= 81).
// (S0,S1) half2, (S2,S3) half2, S4 half -> 10 B/voxel.
__device__ __half2 g_H01[SZ];
__device__ __half2 g_H23[SZ];
__device__ __half  g_H4[SZ];
__device__ double  g_part[K3_BLOCKS];

// ---------------------------------------------------------------------------
// kA: fused W-pass + H-pass, software-pipelined, H-ring in SHARED MEMORY.
// Ring trimmed to 224 cols; with max-shared carveout, 5 blocks/SM fit
// (45.1 KB incl. runtime reserve; 5 x 45.1 = 225 KB <= 228 KB).
// Inner loop identical to the R12 winner.
// ---------------------------------------------------------------------------
__global__ __launch_bounds__(256) void kA(const float* __restrict__ I,
                                          const float* __restrict__ J) {
    __shared__ float4 ringQ[9][WW];     // 32,256 B : (v0,v1,v2,v3) history
    __shared__ float  ringS[9][WW];     //  8,064 B : v4 history
    __shared__ float  sI[2][ROWL];      //  1,856 B
    __shared__ float  sJ[2][ROWL];      //  1,856 B

    const int t = threadIdx.x;
    const int plane = blockIdx.x;              // n*DD + d
    const int h0 = blockIdx.y * CH;
    const float* Ip = I + (size_t)plane * HW;
    const float* Jp = J + (size_t)plane * HW;
    const size_t obase = (size_t)plane * HW;

    const int wld = t - PAD;                   // column this thread loads (halo)
    const bool lane_ok = (t < ROWL);
    const bool ld_ok = lane_ok && ((unsigned)wld < (unsigned)WW);

    // Zero-init ring (column-private; visibility guaranteed by step-0 barrier).
    if (t < WW) {
#pragma unroll
        for (int s = 0; s < 9; s++) {
            ringQ[s][t] = make_float4(0.f, 0.f, 0.f, 0.f);
            ringS[s][t] = 0.f;
        }
    }

    float S0 = 0.f, S1 = 0.f, S2 = 0.f, S3 = 0.f, S4 = 0.f;

    // Prefetch step 0 (row h0 - PAD)
    float vi = 0.f, vj = 0.f;
    {
        const int hh = h0 - PAD;
        if (ld_ok && (unsigned)hh < (unsigned)HH) {
            const size_t p = (size_t)hh * WW + wld;
            vi = Ip[p]; vj = Jp[p];
        }
    }

    int rs = 0;                                // ring slot = step % 9
#pragma unroll 2
    for (int step = 0; step < NSTEPS; step++) {
        const int buf = step & 1;

        // publish prefetched row
        if (lane_ok) {
            sI[buf][t] = vi;
            sJ[buf][t] = vj;
        }

        // prefetch next row (independent of smem/compute)
        {
            const int hh = h0 - PAD + step + 1;
            vi = 0.f; vj = 0.f;
            if (ld_ok && (unsigned)hh < (unsigned)HH) {
                const size_t p = (size_t)hh * WW + wld;
                vi = Ip[p]; vj = Jp[p];
            }
        }

        __syncthreads();

        if (t < WW) {
            float v0 = 0.f, v1 = 0.f, v2 = 0.f, v3 = 0.f, v4 = 0.f;
#pragma unroll
            for (int q = 0; q < 9; q++) {
                const float a = sI[buf][t + q];
                const float b = sJ[buf][t + q];
                v0 += a; v1 += b;
                v2 += a * a; v3 += b * b; v4 += a * b;
            }
            // H sliding window via smem ring (own column only)
            const float4 o4 = ringQ[rs][t];
            const float  o1 = ringS[rs][t];
            S0 += v0 - o4.x;
            S1 += v1 - o4.y;
            S2 += v2 - o4.z;
            S3 += v3 - o4.w;
            S4 += v4 - o1;
            ringQ[rs][t] = make_float4(v0, v1, v2, v3);
            ringS[rs][t] = v4;

            if (step >= 2 * PAD) {
                const int ho = h0 + step - 2 * PAD;
                const size_t idx = obase + (size_t)ho * WW + t;
                g_H01[idx] = __floats2half2_rn(S0, S1);
                g_H23[idx] = __floats2half2_rn(S2, S3);
                g_H4[idx]  = __float2half_rn(S4);
            }
        }
        rs = (rs == 8) ? 0 : rs + 1;
        // no second sync: next step's barrier separates row-buffer reuse
    }
}

// ---------------------------------------------------------------------------
// k3: D-axis sliding box sum + NCC loss + reduction, TWO voxels per thread.
// Paired loads: uint2 (2x half2) for S0S1 and S2S3, half2 for S4 ->
// 3 load instructions per window-side serve 2 voxels (was 3 per voxel).
// ---------------------------------------------------------------------------
__global__ __launch_bounds__(256) void k3_dpass() {
    const int tid = threadIdx.x;
    const int t = blockIdx.x * 256 + tid;      // exact grid: t < T3B

    const int wp = t % W2;                     // voxel-pair index
    int r = t / W2;
    const int h = r % HH; r /= HH;
    const int chunk = r & (NCD - 1);
    const int n = r >> 1;
    const int d0 = chunk * CHD;
    const size_t base = (size_t)n * DHW + (size_t)h * WW + wp * 2;

    const uint2* __restrict__ H01 = reinterpret_cast<const uint2*>(g_H01);
    const uint2* __restrict__ H23 = reinterpret_cast<const uint2*>(g_H23);
    const __half2* __restrict__ H4 = reinterpret_cast<const __half2*>(g_H4);

    float Sa0 = 0.f, Sa1 = 0.f, Sa2 = 0.f, Sa3 = 0.f, Sa4 = 0.f;
    float Sb0 = 0.f, Sb1 = 0.f, Sb2 = 0.f, Sb3 = 0.f, Sb4 = 0.f;

#pragma unroll
    for (int k = -PAD; k <= PAD; k++) {
        const int dd = d0 + k;
        if ((unsigned)dd < (unsigned)DD) {
            const size_t p = (base + (size_t)dd * HW) >> 1;
            const uint2 u01 = H01[p];
            const uint2 u23 = H23[p];
            const float2 a0 = __half22float2(*reinterpret_cast<const __half2*>(&u01.x));
            const float2 a1 = __half22float2(*reinterpret_cast<const __half2*>(&u01.y));
            const float2 b0 = __half22float2(*reinterpret_cast<const __half2*>(&u23.x));
            const float2 b1 = __half22float2(*reinterpret_cast<const __half2*>(&u23.y));
            const float2 g  = __half22float2(H4[p]);
            Sa0 += a0.x; Sa1 += a0.y; Sa2 += b0.x; Sa3 += b0.y; Sa4 += g.x;
            Sb0 += a1.x; Sb1 += a1.y; Sb2 += b1.x; Sb3 += b1.y; Sb4 += g.y;
        }
    }

    const float ws = 729.f, inv_ws = 1.f / 729.f;
    float local = 0.f;

#pragma unroll 4
    for (int d = d0; d < d0 + CHD; d++) {
        {
            const float ui = Sa0 * inv_ws, uj = Sa1 * inv_ws;
            const float cross = Sa4 - uj * Sa0 - ui * Sa1 + ui * uj * ws;
            const float iv = fmaxf(Sa2 - 2.f * ui * Sa0 + ui * ui * ws, EPSV);
            const float jv = fmaxf(Sa3 - 2.f * uj * Sa1 + uj * uj * ws, EPSV);
            local += (cross * cross) / (iv * jv);
        }
        {
            const float ui = Sb0 * inv_ws, uj = Sb1 * inv_ws;
            const float cross = Sb4 - uj * Sb0 - ui * Sb1 + ui * uj * ws;
            const float iv = fmaxf(Sb2 - 2.f * ui * Sb0 + ui * ui * ws, EPSV);
            const float jv = fmaxf(Sb3 - 2.f * uj * Sb1 + uj * uj * ws, EPSV);
            local += (cross * cross) / (iv * jv);
        }

        const int da = d + PAD + 1;
        const int ds = d - PAD;
        if (da < DD) {
            const size_t p = (base + (size_t)da * HW) >> 1;
            const uint2 u01 = H01[p];
            const uint2 u23 = H23[p];
            const float2 a0 = __half22float2(*reinterpret_cast<const __half2*>(&u01.x));
            const float2 a1 = __half22float2(*reinterpret_cast<const __half2*>(&u01.y));
            const float2 b0 = __half22float2(*reinterpret_cast<const __half2*>(&u23.x));
            const float2 b1 = __half22float2(*reinterpret_cast<const __half2*>(&u23.y));
            const float2 g  = __half22float2(H4[p]);
            Sa0 += a0.x; Sa1 += a0.y; Sa2 += b0.x; Sa3 += b0.y; Sa4 += g.x;
            Sb0 += a1.x; Sb1 += a1.y; Sb2 += b1.x; Sb3 += b1.y; Sb4 += g.y;
        }
        if (ds >= 0) {
            const size_t p = (base + (size_t)ds * HW) >> 1;
            const uint2 u01 = H01[p];
            const uint2 u23 = H23[p];
            const float2 a0 = __half22float2(*reinterpret_cast<const __half2*>(&u01.x));
            const float2 a1 = __half22float2(*reinterpret_cast<const __half2*>(&u01.y));
            const float2 b0 = __half22float2(*reinterpret_cast<const __half2*>(&u23.x));
            const float2 b1 = __half22float2(*reinterpret_cast<const __half2*>(&u23.y));
            const float2 g  = __half22float2(H4[p]);
            Sa0 -= a0.x; Sa1 -= a0.y; Sa2 -= b0.x; Sa3 -= b0.y; Sa4 -= g.x;
            Sb0 -= a1.x; Sb1 -= a1.y; Sb2 -= b1.x; Sb3 -= b1.y; Sb4 -= g.y;
        }
    }

#pragma unroll
    for (int o = 16; o > 0; o >>= 1)
        local += __shfl_down_sync(0xffffffffu, local, o);

    __shared__ float wsum[8];
    if ((tid & 31) == 0) wsum[tid >> 5] = local;
    __syncthreads();
    if (tid == 0) {
        float s = 0.f;
#pragma unroll
        for (int i = 0; i < 8; i++) s += wsum[i];
        g_part[blockIdx.x] = (double)s;
    }
}

// ---------------------------------------------------------------------------
// Final: parallel deterministic reduction of 336 partials.
// ---------------------------------------------------------------------------
__global__ __launch_bounds__(256) void k_final(float* __restrict__ out) {
    __shared__ double sd[256];
    const int t = threadIdx.x;
    double s = 0.0;
    for (int i = t; i < K3_BLOCKS; i += 256) s += g_part[i];
    sd[t] = s;
    __syncthreads();
#pragma unroll
    for (int o = 128; o > 0; o >>= 1) {
        if (t < o) sd[t] += sd[t + o];
        __syncthreads();
    }
    if (t == 0) out[0] = (float)(-sd[0] / (double)VOLI);
}

extern "C" void kernel_launch(void* const* d_in, const int* in_sizes, int n_in,
                              void* d_out, int out_size) {
    const float* I = (const float*)d_in[0];   // y_true
    const float* J = (const float*)d_in[1];   // y_pred

    // Max-shared carveout so 5 kA blocks/SM fit (idempotent, immediate API).
    cudaFuncSetAttribute((const void*)kA,
                         cudaFuncAttributePreferredSharedMemoryCarveout, 100);

    dim3 gridA(NB * DD, HH / CH);             // (320, 3)
    kA<<<gridA, 256>>>(I, J);
    k3_dpass<<<K3_BLOCKS, 256>>>();
    k_final<<<1, 256>>>((float*)d_out);
}

// round 14
// speedup vs baseline: 1.5364x; 1.5364x over previous
#include <cuda_runtime.h>
#include <cuda_fp16.h>

// Geometry: (N=2, C=1, D=160, H=192, W=224), win=9, pad=4, zero-padded box sums.
#define NB   2
#define DD   160
#define HH   192
#define WW   224
#define HW   (HH * WW)            // 43008
#define DHW  (DD * HW)            // 6881280
#define VOLI (NB * DHW)           // 13762560
#define PAD  4
#define EPSV 1e-5f
#define SZ   ((size_t)VOLI)

#define CH     64                 // h-chunk per block in kA
#define NSTEPS (CH + 2 * PAD)     // 72
#define ROWL   (WW + 2 * PAD)     // 232

#define CHD  40                   // d-chunk per thread in k3 (was 80)
#define NCD  4
#define T3   (NB * NCD * HH * WW) // 344064
#define K3_BLOCKS (T3 / 256)      // 1344

// Scratch: W+H box-summed fields in FP16 (values <= 81, fits easily).
// 3 streams: (S0,S1) half2, (S2,S3) half2, S4 half  -> 10 B/voxel.
__device__ __half2 g_H01[SZ];
__device__ __half2 g_H23[SZ];
__device__ __half  g_H4[SZ];
__device__ double  g_part[K3_BLOCKS];

// ---------------------------------------------------------------------------
// kA: fused W-pass + H-pass, software-pipelined, H-ring in SHARED MEMORY.
// (R12 winner verbatim: 232-column ring, fp16 epilogue, no carveout games.)
// ---------------------------------------------------------------------------
__global__ __launch_bounds__(256) void kA(const float* __restrict__ I,
                                          const float* __restrict__ J) {
    __shared__ float4 ringQ[9][ROWL];   // 33,408 B : (v0,v1,v2,v3) history
    __shared__ float  ringS[9][ROWL];   //  8,352 B : v4 history
    __shared__ float  sI[2][ROWL];      //  1,856 B
    __shared__ float  sJ[2][ROWL];      //  1,856 B

    const int t = threadIdx.x;
    const int plane = blockIdx.x;              // n*DD + d
    const int h0 = blockIdx.y * CH;
    const float* Ip = I + (size_t)plane * HW;
    const float* Jp = J + (size_t)plane * HW;
    const size_t obase = (size_t)plane * HW;

    const int wld = t - PAD;                   // column this thread loads (halo)
    const bool lane_ok = (t < ROWL);
    const bool ld_ok = lane_ok && ((unsigned)wld < (unsigned)WW);

    // Zero-init ring (column-private; visibility guaranteed by step-0 barrier).
    if (t < ROWL) {
#pragma unroll
        for (int s = 0; s < 9; s++) {
            ringQ[s][t] = make_float4(0.f, 0.f, 0.f, 0.f);
            ringS[s][t] = 0.f;
        }
    }

    float S0 = 0.f, S1 = 0.f, S2 = 0.f, S3 = 0.f, S4 = 0.f;

    // Prefetch step 0 (row h0 - PAD)
    float vi = 0.f, vj = 0.f;
    {
        const int hh = h0 - PAD;
        if (ld_ok && (unsigned)hh < (unsigned)HH) {
            const size_t p = (size_t)hh * WW + wld;
            vi = Ip[p]; vj = Jp[p];
        }
    }

    int rs = 0;                                // ring slot = step % 9
#pragma unroll 2
    for (int step = 0; step < NSTEPS; step++) {
        const int buf = step & 1;

        // publish prefetched row
        if (lane_ok) {
            sI[buf][t] = vi;
            sJ[buf][t] = vj;
        }

        // prefetch next row (independent of smem/compute)
        {
            const int hh = h0 - PAD + step + 1;
            vi = 0.f; vj = 0.f;
            if (ld_ok && (unsigned)hh < (unsigned)HH) {
                const size_t p = (size_t)hh * WW + wld;
                vi = Ip[p]; vj = Jp[p];
            }
        }

        __syncthreads();

        if (t < WW) {
            float v0 = 0.f, v1 = 0.f, v2 = 0.f, v3 = 0.f, v4 = 0.f;
#pragma unroll
            for (int q = 0; q < 9; q++) {
                const float a = sI[buf][t + q];
                const float b = sJ[buf][t + q];
                v0 += a; v1 += b;
                v2 += a * a; v3 += b * b; v4 += a * b;
            }
            // H sliding window via smem ring (own column only)
            const float4 o4 = ringQ[rs][t];
            const float  o1 = ringS[rs][t];
            S0 += v0 - o4.x;
            S1 += v1 - o4.y;
            S2 += v2 - o4.z;
            S3 += v3 - o4.w;
            S4 += v4 - o1;
            ringQ[rs][t] = make_float4(v0, v1, v2, v3);
            ringS[rs][t] = v4;

            if (step >= 2 * PAD) {
                const int ho = h0 + step - 2 * PAD;
                const size_t idx = obase + (size_t)ho * WW + t;
                g_H01[idx] = __floats2half2_rn(S0, S1);
                g_H23[idx] = __floats2half2_rn(S2, S3);
                g_H4[idx]  = __float2half_rn(S4);
            }
        }
        rs = (rs == 8) ? 0 : rs + 1;
        // no second sync: next step's barrier separates row-buffer reuse
    }
}

// ---------------------------------------------------------------------------
// k3: D-axis sliding box sum fused with NCC pointwise loss + block reduction.
// (R12 algorithm; D split into 4 chunks of 40 -> 1344 blocks, ~9/SM, for
// latency hiding. +11% window-init reads, negligible bytes.)
// ---------------------------------------------------------------------------
__global__ __launch_bounds__(256) void k3_dpass() {
    const int tid = threadIdx.x;
    const int t = blockIdx.x * 256 + tid;
    float local = 0.f;

    if (t < T3) {
        int w = t % WW;
        int r = t / WW;
        int h = r % HH; r /= HH;
        int chunk = r & (NCD - 1);
        int n = r >> 2;
        int d0 = chunk * CHD;
        size_t base = (size_t)n * DHW + (size_t)h * WW + w;

        float S0 = 0.f, S1 = 0.f, S2 = 0.f, S3 = 0.f, S4 = 0.f;
#pragma unroll
        for (int k = -PAD; k <= PAD; k++) {
            int dd = d0 + k;
            if ((unsigned)dd < (unsigned)DD) {
                size_t p = base + (size_t)dd * HW;
                const float2 a = __half22float2(g_H01[p]);
                const float2 b = __half22float2(g_H23[p]);
                S0 += a.x; S1 += a.y; S2 += b.x; S3 += b.y;
                S4 += __half2float(g_H4[p]);
            }
        }

        const float ws = 729.f, inv_ws = 1.f / 729.f;

#pragma unroll 4
        for (int d = d0; d < d0 + CHD; d++) {
            float ui = S0 * inv_ws;
            float uj = S1 * inv_ws;
            float cross = S4 - uj * S0 - ui * S1 + ui * uj * ws;
            float iv = fmaxf(S2 - 2.f * ui * S0 + ui * ui * ws, EPSV);
            float jv = fmaxf(S3 - 2.f * uj * S1 + uj * uj * ws, EPSV);
            local += (cross * cross) / (iv * jv);

            int da = d + PAD + 1;
            int ds = d - PAD;
            if (da < DD) {
                size_t q = base + (size_t)da * HW;
                const float2 a = __half22float2(g_H01[q]);
                const float2 b = __half22float2(g_H23[q]);
                S0 += a.x; S1 += a.y; S2 += b.x; S3 += b.y;
                S4 += __half2float(g_H4[q]);
            }
            if (ds >= 0) {
                size_t q = base + (size_t)ds * HW;
                const float2 a = __half22float2(g_H01[q]);
                const float2 b = __half22float2(g_H23[q]);
                S0 -= a.x; S1 -= a.y; S2 -= b.x; S3 -= b.y;
                S4 -= __half2float(g_H4[q]);
            }
        }
    }

#pragma unroll
    for (int o = 16; o > 0; o >>= 1)
        local += __shfl_down_sync(0xffffffffu, local, o);

    __shared__ float wsum[8];
    if ((tid & 31) == 0) wsum[tid >> 5] = local;
    __syncthreads();
    if (tid == 0) {
        float s = 0.f;
#pragma unroll
        for (int i = 0; i < 8; i++) s += wsum[i];
        g_part[blockIdx.x] = (double)s;
    }
}

// ---------------------------------------------------------------------------
// Final: parallel deterministic reduction of 1344 partials.
// ---------------------------------------------------------------------------
__global__ __launch_bounds__(256) void k_final(float* __restrict__ out) {
    __shared__ double sd[256];
    const int t = threadIdx.x;
    double s = 0.0;
    for (int i = t; i < K3_BLOCKS; i += 256) s += g_part[i];
    sd[t] = s;
    __syncthreads();
#pragma unroll
    for (int o = 128; o > 0; o >>= 1) {
        if (t < o) sd[t] += sd[t + o];
        __syncthreads();
    }
    if (t == 0) out[0] = (float)(-sd[0] / (double)VOLI);
}

extern "C" void kernel_launch(void* const* d_in, const int* in_sizes, int n_in,
                              void* d_out, int out_size) {
    const float* I = (const float*)d_in[0];   // y_true
    const float* J = (const float*)d_in[1];   // y_pred

    dim3 gridA(NB * DD, HH / CH);             // (320, 3)
    kA<<<gridA, 256>>>(I, J);
    k3_dpass<<<K3_BLOCKS, 256>>>();
    k_final<<<1, 256>>>((float*)d_out);
}

// round 15
// speedup vs baseline: 1.6118x; 1.0490x over previous
#include <cuda_runtime.h>
#include <cuda_fp16.h>

// Geometry: (N=2, C=1, D=160, H=192, W=224), win=9, pad=4, zero-padded box sums.
#define NB   2
#define DD   160
#define HH   192
#define WW   224
#define HW   (HH * WW)            // 43008
#define DHW  (DD * HW)            // 6881280
#define VOLI (NB * DHW)           // 13762560
#define PAD  4
#define EPSV 1e-5f
#define SZ   ((size_t)VOLI)

#define CH     64                 // h-chunk per block in kA
#define NSTEPS (CH + 2 * PAD)     // 72
#define ROWL   (WW + 2 * PAD)     // 232

#define CHD  40                   // d-chunk per thread in k3
#define NCD  4
#define W2   (WW / 2)             // 112 voxel-pairs per row
#define T3B  (NB * NCD * HH * W2) // 172032 threads (2 voxels each)
#define K3_BLOCKS (T3B / 256)     // 672

// Scratch: W+H box-summed fields in FP16 (values <= 81).
// (S0,S1) half2, (S2,S3) half2, S4 half -> 10 B/voxel.
__device__ __half2 g_H01[SZ];
__device__ __half2 g_H23[SZ];
__device__ __half  g_H4[SZ];
__device__ double  g_part[K3_BLOCKS];

// ---------------------------------------------------------------------------
// kA: fused W-pass + H-pass, software-pipelined.
// FP16 smem: rows packed half2(I,J) -> 9 LDS.32 taps move half the bytes;
// ring packed half2/half2/half -> 10B instead of 20B. Accumulators stay fp32;
// ring add/sub both use the fp16-rounded value, so the window is drift-free.
// Block smem ~23KB -> warp-limited 8 blocks/SM.
// ---------------------------------------------------------------------------
__global__ __launch_bounds__(256) void kA(const float* __restrict__ I,
                                          const float* __restrict__ J) {
    __shared__ __half2 ringA[9][ROWL];  // 8,352 B : (v0,v1)
    __shared__ __half2 ringB[9][ROWL];  // 8,352 B : (v2,v3)
    __shared__ __half  ringC[9][ROWL];  // 4,176 B : v4
    __shared__ __half2 sRow[2][ROWL];   // 1,856 B : packed (I,J) rows

    const int t = threadIdx.x;
    const int plane = blockIdx.x;              // n*DD + d
    const int h0 = blockIdx.y * CH;
    const float* Ip = I + (size_t)plane * HW;
    const float* Jp = J + (size_t)plane * HW;
    const size_t obase = (size_t)plane * HW;

    const int wld = t - PAD;                   // column this thread loads (halo)
    const bool lane_ok = (t < ROWL);
    const bool ld_ok = lane_ok && ((unsigned)wld < (unsigned)WW);

    // Zero-init ring (column-private; visibility guaranteed by step-0 barrier).
    if (t < ROWL) {
        const __half2 z2 = __floats2half2_rn(0.f, 0.f);
#pragma unroll
        for (int s = 0; s < 9; s++) {
            ringA[s][t] = z2;
            ringB[s][t] = z2;
            ringC[s][t] = __float2half_rn(0.f);
        }
    }

    float S0 = 0.f, S1 = 0.f, S2 = 0.f, S3 = 0.f, S4 = 0.f;

    // Prefetch step 0 (row h0 - PAD)
    float vi = 0.f, vj = 0.f;
    {
        const int hh = h0 - PAD;
        if (ld_ok && (unsigned)hh < (unsigned)HH) {
            const size_t p = (size_t)hh * WW + wld;
            vi = Ip[p]; vj = Jp[p];
        }
    }

    int rs = 0;                                // ring slot = step % 9
#pragma unroll 2
    for (int step = 0; step < NSTEPS; step++) {
        const int buf = step & 1;

        // publish prefetched row (packed fp16)
        if (lane_ok) sRow[buf][t] = __floats2half2_rn(vi, vj);

        // prefetch next row (independent of smem/compute)
        {
            const int hh = h0 - PAD + step + 1;
            vi = 0.f; vj = 0.f;
            if (ld_ok && (unsigned)hh < (unsigned)HH) {
                const size_t p = (size_t)hh * WW + wld;
                vi = Ip[p]; vj = Jp[p];
            }
        }

        __syncthreads();

        if (t < WW) {
            float v0 = 0.f, v1 = 0.f, v2 = 0.f, v3 = 0.f, v4 = 0.f;
#pragma unroll
            for (int q = 0; q < 9; q++) {
                const float2 ab = __half22float2(sRow[buf][t + q]);
                v0 += ab.x; v1 += ab.y;
                v2 += ab.x * ab.x; v3 += ab.y * ab.y; v4 += ab.x * ab.y;
            }
            // Round v to fp16 once; use the rounded values on BOTH the add and
            // (9 steps later) the subtract side -> exact cancellation.
            const __half2 n01 = __floats2half2_rn(v0, v1);
            const __half2 n23 = __floats2half2_rn(v2, v3);
            const __half  n4  = __float2half_rn(v4);
            const float2 vr01 = __half22float2(n01);
            const float2 vr23 = __half22float2(n23);
            const float  vr4  = __half2float(n4);

            const float2 o01 = __half22float2(ringA[rs][t]);
            const float2 o23 = __half22float2(ringB[rs][t]);
            const float  o4  = __half2float(ringC[rs][t]);

            S0 += vr01.x - o01.x;
            S1 += vr01.y - o01.y;
            S2 += vr23.x - o23.x;
            S3 += vr23.y - o23.y;
            S4 += vr4    - o4;

            ringA[rs][t] = n01;
            ringB[rs][t] = n23;
            ringC[rs][t] = n4;

            if (step >= 2 * PAD) {
                const int ho = h0 + step - 2 * PAD;
                const size_t idx = obase + (size_t)ho * WW + t;
                g_H01[idx] = __floats2half2_rn(S0, S1);
                g_H23[idx] = __floats2half2_rn(S2, S3);
                g_H4[idx]  = __float2half_rn(S4);
            }
        }
        rs = (rs == 8) ? 0 : rs + 1;
        // no second sync: next step's barrier separates row-buffer reuse
    }
}

// ---------------------------------------------------------------------------
// k3: D-axis sliding box sum + NCC loss + reduction, TWO voxels per thread,
// NCD=4 so the grid stays at 672 blocks (R13's packing at 336 blocks starved
// latency hiding; this keeps concurrency while halving load instructions).
// ---------------------------------------------------------------------------
__global__ __launch_bounds__(256) void k3_dpass() {
    const int tid = threadIdx.x;
    const int t = blockIdx.x * 256 + tid;      // exact grid: t < T3B

    const int wp = t % W2;                     // voxel-pair index
    int r = t / W2;
    const int h = r % HH; r /= HH;
    const int chunk = r & (NCD - 1);
    const int n = r >> 2;
    const int d0 = chunk * CHD;
    const size_t base = (size_t)n * DHW + (size_t)h * WW + wp * 2;

    const uint2* __restrict__ H01 = reinterpret_cast<const uint2*>(g_H01);
    const uint2* __restrict__ H23 = reinterpret_cast<const uint2*>(g_H23);
    const __half2* __restrict__ H4 = reinterpret_cast<const __half2*>(g_H4);

    float Sa0 = 0.f, Sa1 = 0.f, Sa2 = 0.f, Sa3 = 0.f, Sa4 = 0.f;
    float Sb0 = 0.f, Sb1 = 0.f, Sb2 = 0.f, Sb3 = 0.f, Sb4 = 0.f;

#pragma unroll
    for (int k = -PAD; k <= PAD; k++) {
        const int dd = d0 + k;
        if ((unsigned)dd < (unsigned)DD) {
            const size_t p = (base + (size_t)dd * HW) >> 1;
            const uint2 u01 = H01[p];
            const uint2 u23 = H23[p];
            const float2 a0 = __half22float2(*reinterpret_cast<const __half2*>(&u01.x));
            const float2 a1 = __half22float2(*reinterpret_cast<const __half2*>(&u01.y));
            const float2 b0 = __half22float2(*reinterpret_cast<const __half2*>(&u23.x));
            const float2 b1 = __half22float2(*reinterpret_cast<const __half2*>(&u23.y));
            const float2 g  = __half22float2(H4[p]);
            Sa0 += a0.x; Sa1 += a0.y; Sa2 += b0.x; Sa3 += b0.y; Sa4 += g.x;
            Sb0 += a1.x; Sb1 += a1.y; Sb2 += b1.x; Sb3 += b1.y; Sb4 += g.y;
        }
    }

    const float ws = 729.f, inv_ws = 1.f / 729.f;
    float local = 0.f;

#pragma unroll 4
    for (int d = d0; d < d0 + CHD; d++) {
        {
            const float ui = Sa0 * inv_ws, uj = Sa1 * inv_ws;
            const float cross = Sa4 - uj * Sa0 - ui * Sa1 + ui * uj * ws;
            const float iv = fmaxf(Sa2 - 2.f * ui * Sa0 + ui * ui * ws, EPSV);
            const float jv = fmaxf(Sa3 - 2.f * uj * Sa1 + uj * uj * ws, EPSV);
            local += (cross * cross) / (iv * jv);
        }
        {
            const float ui = Sb0 * inv_ws, uj = Sb1 * inv_ws;
            const float cross = Sb4 - uj * Sb0 - ui * Sb1 + ui * uj * ws;
            const float iv = fmaxf(Sb2 - 2.f * ui * Sb0 + ui * ui * ws, EPSV);
            const float jv = fmaxf(Sb3 - 2.f * uj * Sb1 + uj * uj * ws, EPSV);
            local += (cross * cross) / (iv * jv);
        }

        const int da = d + PAD + 1;
        const int ds = d - PAD;
        if (da < DD) {
            const size_t p = (base + (size_t)da * HW) >> 1;
            const uint2 u01 = H01[p];
            const uint2 u23 = H23[p];
            const float2 a0 = __half22float2(*reinterpret_cast<const __half2*>(&u01.x));
            const float2 a1 = __half22float2(*reinterpret_cast<const __half2*>(&u01.y));
            const float2 b0 = __half22float2(*reinterpret_cast<const __half2*>(&u23.x));
            const float2 b1 = __half22float2(*reinterpret_cast<const __half2*>(&u23.y));
            const float2 g  = __half22float2(H4[p]);
            Sa0 += a0.x; Sa1 += a0.y; Sa2 += b0.x; Sa3 += b0.y; Sa4 += g.x;
            Sb0 += a1.x; Sb1 += a1.y; Sb2 += b1.x; Sb3 += b1.y; Sb4 += g.y;
        }
        if (ds >= 0) {
            const size_t p = (base + (size_t)ds * HW) >> 1;
            const uint2 u01 = H01[p];
            const uint2 u23 = H23[p];
            const float2 a0 = __half22float2(*reinterpret_cast<const __half2*>(&u01.x));
            const float2 a1 = __half22float2(*reinterpret_cast<const __half2*>(&u01.y));
            const float2 b0 = __half22float2(*reinterpret_cast<const __half2*>(&u23.x));
            const float2 b1 = __half22float2(*reinterpret_cast<const __half2*>(&u23.y));
            const float2 g  = __half22float2(H4[p]);
            Sa0 -= a0.x; Sa1 -= a0.y; Sa2 -= b0.x; Sa3 -= b0.y; Sa4 -= g.x;
            Sb0 -= a1.x; Sb1 -= a1.y; Sb2 -= b1.x; Sb3 -= b1.y; Sb4 -= g.y;
        }
    }

#pragma unroll
    for (int o = 16; o > 0; o >>= 1)
        local += __shfl_down_sync(0xffffffffu, local, o);

    __shared__ float wsum[8];
    if ((tid & 31) == 0) wsum[tid >> 5] = local;
    __syncthreads();
    if (tid == 0) {
        float s = 0.f;
#pragma unroll
        for (int i = 0; i < 8; i++) s += wsum[i];
        g_part[blockIdx.x] = (double)s;
    }
}

// ---------------------------------------------------------------------------
// Final: parallel deterministic reduction of 672 partials.
// ---------------------------------------------------------------------------
__global__ __launch_bounds__(256) void k_final(float* __restrict__ out) {
    __shared__ double sd[256];
    const int t = threadIdx.x;
    double s = 0.0;
    for (int i = t; i < K3_BLOCKS; i += 256) s += g_part[i];
    sd[t] = s;
    __syncthreads();
#pragma unroll
    for (int o = 128; o > 0; o >>= 1) {
        if (t < o) sd[t] += sd[t + o];
        __syncthreads();
    }
    if (t == 0) out[0] = (float)(-sd[0] / (double)VOLI);
}

extern "C" void kernel_launch(void* const* d_in, const int* in_sizes, int n_in,
                              void* d_out, int out_size) {
    const float* I = (const float*)d_in[0];   // y_true
    const float* J = (const float*)d_in[1];   // y_pred

    dim3 gridA(NB * DD, HH / CH);             // (320, 3)
    kA<<<gridA, 256>>>(I, J);
    k3_dpass<<<K3_BLOCKS, 256>>>();
    k_final<<<1, 256>>>((float*)d_out);
}

// round 16
// speedup vs baseline: 1.7279x; 1.0721x over previous
#include <cuda_runtime.h>
#include <cuda_fp16.h>

// Geometry: (N=2, C=1, D=160, H=192, W=224), win=9, pad=4, zero-padded box sums.
#define NB   2
#define DD   160
#define HH   192
#define WW   224
#define HW   (HH * WW)            // 43008
#define DHW  (DD * HW)            // 6881280
#define VOLI (NB * DHW)           // 13762560
#define PAD  4
#define EPSV 1e-5f
#define SZ   ((size_t)VOLI)

#define CH     64                 // h-chunk per block in kA
#define NSTEPS (CH + 2 * PAD)     // 72
#define ROWL   (WW + 2 * PAD)     // 232

#define CHD  40                   // d-chunk per thread in k3
#define NCD  4
#define W2   (WW / 2)             // 112 voxel-pairs per row
#define T3B  (NB * NCD * HH * W2) // 172032 threads (2 voxels each)
#define K3_BLOCKS (T3B / 256)     // 672

// Scratch: W+H box-summed fields in FP16 (values <= 81).
// (S0,S1) half2, (S2,S3) half2, S4 half -> 10 B/voxel.
__device__ __half2 g_H01[SZ];
__device__ __half2 g_H23[SZ];
__device__ __half  g_H4[SZ];
__device__ double  g_part[K3_BLOCKS];

// ---------------------------------------------------------------------------
// kA: fused W-pass + H-pass, software-pipelined, H-ring in SHARED MEMORY.
// (R12/R14 winner verbatim: fp32 smem rows + fp32 ring, fp16 global epilogue.
//  Measured 85.5us twice; R15's fp16-smem variant was issue-bound at 95.5us.)
// ---------------------------------------------------------------------------
__global__ __launch_bounds__(256) void kA(const float* __restrict__ I,
                                          const float* __restrict__ J) {
    __shared__ float4 ringQ[9][ROWL];   // 33,408 B : (v0,v1,v2,v3) history
    __shared__ float  ringS[9][ROWL];   //  8,352 B : v4 history
    __shared__ float  sI[2][ROWL];      //  1,856 B
    __shared__ float  sJ[2][ROWL];      //  1,856 B

    const int t = threadIdx.x;
    const int plane = blockIdx.x;              // n*DD + d
    const int h0 = blockIdx.y * CH;
    const float* Ip = I + (size_t)plane * HW;
    const float* Jp = J + (size_t)plane * HW;
    const size_t obase = (size_t)plane * HW;

    const int wld = t - PAD;                   // column this thread loads (halo)
    const bool lane_ok = (t < ROWL);
    const bool ld_ok = lane_ok && ((unsigned)wld < (unsigned)WW);

    // Zero-init ring (column-private; visibility guaranteed by step-0 barrier).
    if (t < ROWL) {
#pragma unroll
        for (int s = 0; s < 9; s++) {
            ringQ[s][t] = make_float4(0.f, 0.f, 0.f, 0.f);
            ringS[s][t] = 0.f;
        }
    }

    float S0 = 0.f, S1 = 0.f, S2 = 0.f, S3 = 0.f, S4 = 0.f;

    // Prefetch step 0 (row h0 - PAD)
    float vi = 0.f, vj = 0.f;
    {
        const int hh = h0 - PAD;
        if (ld_ok && (unsigned)hh < (unsigned)HH) {
            const size_t p = (size_t)hh * WW + wld;
            vi = Ip[p]; vj = Jp[p];
        }
    }

    int rs = 0;                                // ring slot = step % 9
#pragma unroll 2
    for (int step = 0; step < NSTEPS; step++) {
        const int buf = step & 1;

        // publish prefetched row
        if (lane_ok) {
            sI[buf][t] = vi;
            sJ[buf][t] = vj;
        }

        // prefetch next row (independent of smem/compute)
        {
            const int hh = h0 - PAD + step + 1;
            vi = 0.f; vj = 0.f;
            if (ld_ok && (unsigned)hh < (unsigned)HH) {
                const size_t p = (size_t)hh * WW + wld;
                vi = Ip[p]; vj = Jp[p];
            }
        }

        __syncthreads();

        if (t < WW) {
            float v0 = 0.f, v1 = 0.f, v2 = 0.f, v3 = 0.f, v4 = 0.f;
#pragma unroll
            for (int q = 0; q < 9; q++) {
                const float a = sI[buf][t + q];
                const float b = sJ[buf][t + q];
                v0 += a; v1 += b;
                v2 += a * a; v3 += b * b; v4 += a * b;
            }
            // H sliding window via smem ring (own column only)
            const float4 o4 = ringQ[rs][t];
            const float  o1 = ringS[rs][t];
            S0 += v0 - o4.x;
            S1 += v1 - o4.y;
            S2 += v2 - o4.z;
            S3 += v3 - o4.w;
            S4 += v4 - o1;
            ringQ[rs][t] = make_float4(v0, v1, v2, v3);
            ringS[rs][t] = v4;

            if (step >= 2 * PAD) {
                const int ho = h0 + step - 2 * PAD;
                const size_t idx = obase + (size_t)ho * WW + t;
                g_H01[idx] = __floats2half2_rn(S0, S1);
                g_H23[idx] = __floats2half2_rn(S2, S3);
                g_H4[idx]  = __float2half_rn(S4);
            }
        }
        rs = (rs == 8) ? 0 : rs + 1;
        // no second sync: next step's barrier separates row-buffer reuse
    }
}

// ---------------------------------------------------------------------------
// k3: D-axis sliding box sum + NCC loss + reduction, TWO voxels per thread,
// NCD=4 -> 672 blocks. (R15 winner verbatim, ~58us measured.)
// ---------------------------------------------------------------------------
__global__ __launch_bounds__(256) void k3_dpass() {
    const int tid = threadIdx.x;
    const int t = blockIdx.x * 256 + tid;      // exact grid: t < T3B

    const int wp = t % W2;                     // voxel-pair index
    int r = t / W2;
    const int h = r % HH; r /= HH;
    const int chunk = r & (NCD - 1);
    const int n = r >> 2;
    const int d0 = chunk * CHD;
    const size_t base = (size_t)n * DHW + (size_t)h * WW + wp * 2;

    const uint2* __restrict__ H01 = reinterpret_cast<const uint2*>(g_H01);
    const uint2* __restrict__ H23 = reinterpret_cast<const uint2*>(g_H23);
    const __half2* __restrict__ H4 = reinterpret_cast<const __half2*>(g_H4);

    float Sa0 = 0.f, Sa1 = 0.f, Sa2 = 0.f, Sa3 = 0.f, Sa4 = 0.f;
    float Sb0 = 0.f, Sb1 = 0.f, Sb2 = 0.f, Sb3 = 0.f, Sb4 = 0.f;

#pragma unroll
    for (int k = -PAD; k <= PAD; k++) {
        const int dd = d0 + k;
        if ((unsigned)dd < (unsigned)DD) {
            const size_t p = (base + (size_t)dd * HW) >> 1;
            const uint2 u01 = H01[p];
            const uint2 u23 = H23[p];
            const float2 a0 = __half22float2(*reinterpret_cast<const __half2*>(&u01.x));
            const float2 a1 = __half22float2(*reinterpret_cast<const __half2*>(&u01.y));
            const float2 b0 = __half22float2(*reinterpret_cast<const __half2*>(&u23.x));
            const float2 b1 = __half22float2(*reinterpret_cast<const __half2*>(&u23.y));
            const float2 g  = __half22float2(H4[p]);
            Sa0 += a0.x; Sa1 += a0.y; Sa2 += b0.x; Sa3 += b0.y; Sa4 += g.x;
            Sb0 += a1.x; Sb1 += a1.y; Sb2 += b1.x; Sb3 += b1.y; Sb4 += g.y;
        }
    }

    const float ws = 729.f, inv_ws = 1.f / 729.f;
    float local = 0.f;

#pragma unroll 4
    for (int d = d0; d < d0 + CHD; d++) {
        {
            const float ui = Sa0 * inv_ws, uj = Sa1 * inv_ws;
            const float cross = Sa4 - uj * Sa0 - ui * Sa1 + ui * uj * ws;
            const float iv = fmaxf(Sa2 - 2.f * ui * Sa0 + ui * ui * ws, EPSV);
            const float jv = fmaxf(Sa3 - 2.f * uj * Sa1 + uj * uj * ws, EPSV);
            local += (cross * cross) / (iv * jv);
        }
        {
            const float ui = Sb0 * inv_ws, uj = Sb1 * inv_ws;
            const float cross = Sb4 - uj * Sb0 - ui * Sb1 + ui * uj * ws;
            const float iv = fmaxf(Sb2 - 2.f * ui * Sb0 + ui * ui * ws, EPSV);
            const float jv = fmaxf(Sb3 - 2.f * uj * Sb1 + uj * uj * ws, EPSV);
            local += (cross * cross) / (iv * jv);
        }

        const int da = d + PAD + 1;
        const int ds = d - PAD;
        if (da < DD) {
            const size_t p = (base + (size_t)da * HW) >> 1;
            const uint2 u01 = H01[p];
            const uint2 u23 = H23[p];
            const float2 a0 = __half22float2(*reinterpret_cast<const __half2*>(&u01.x));
            const float2 a1 = __half22float2(*reinterpret_cast<const __half2*>(&u01.y));
            const float2 b0 = __half22float2(*reinterpret_cast<const __half2*>(&u23.x));
            const float2 b1 = __half22float2(*reinterpret_cast<const __half2*>(&u23.y));
            const float2 g  = __half22float2(H4[p]);
            Sa0 += a0.x; Sa1 += a0.y; Sa2 += b0.x; Sa3 += b0.y; Sa4 += g.x;
            Sb0 += a1.x; Sb1 += a1.y; Sb2 += b1.x; Sb3 += b1.y; Sb4 += g.y;
        }
        if (ds >= 0) {
            const size_t p = (base + (size_t)ds * HW) >> 1;
            const uint2 u01 = H01[p];
            const uint2 u23 = H23[p];
            const float2 a0 = __half22float2(*reinterpret_cast<const __half2*>(&u01.x));
            const float2 a1 = __half22float2(*reinterpret_cast<const __half2*>(&u01.y));
            const float2 b0 = __half22float2(*reinterpret_cast<const __half2*>(&u23.x));
            const float2 b1 = __half22float2(*reinterpret_cast<const __half2*>(&u23.y));
            const float2 g  = __half22float2(H4[p]);
            Sa0 -= a0.x; Sa1 -= a0.y; Sa2 -= b0.x; Sa3 -= b0.y; Sa4 -= g.x;
            Sb0 -= a1.x; Sb1 -= a1.y; Sb2 -= b1.x; Sb3 -= b1.y; Sb4 -= g.y;
        }
    }

#pragma unroll
    for (int o = 16; o > 0; o >>= 1)
        local += __shfl_down_sync(0xffffffffu, local, o);

    __shared__ float wsum[8];
    if ((tid & 31) == 0) wsum[tid >> 5] = local;
    __syncthreads();
    if (tid == 0) {
        float s = 0.f;
#pragma unroll
        for (int i = 0; i < 8; i++) s += wsum[i];
        g_part[blockIdx.x] = (double)s;
    }
}

// ---------------------------------------------------------------------------
// Final: parallel deterministic reduction of 672 partials.
// ---------------------------------------------------------------------------
__global__ __launch_bounds__(256) void k_final(float* __restrict__ out) {
    __shared__ double sd[256];
    const int t = threadIdx.x;
    double s = 0.0;
    for (int i = t; i < K3_BLOCKS; i += 256) s += g_part[i];
    sd[t] = s;
    __syncthreads();
#pragma unroll
    for (int o = 128; o > 0; o >>= 1) {
        if (t < o) sd[t] += sd[t + o];
        __syncthreads();
    }
    if (t == 0) out[0] = (float)(-sd[0] / (double)VOLI);
}

extern "C" void kernel_launch(void* const* d_in, const int* in_sizes, int n_in,
                              void* d_out, int out_size) {
    const float* I = (const float*)d_in[0];   // y_true
    const float* J = (const float*)d_in[1];   // y_pred

    dim3 gridA(NB * DD, HH / CH);             // (320, 3)
    kA<<<gridA, 256>>>(I, J);
    k3_dpass<<<K3_BLOCKS, 256>>>();
    k_final<<<1, 256>>>((float*)d_out);
}